// round 5
// baseline (speedup 1.0000x reference)
#include <cuda_runtime.h>
#include <cuda_bf16.h>
#include <math.h>

// ---------------------------------------------------------------------------
// SupPatchNCELoss — GB300 (sm_103a)
//
// loss = mean_i [ log S1_i - (S2_i - cnt_i) * (1/T) / cnt_i ]
//   S1_i = sum_{j!=i} exp((cos_ij - 1)/T)     (shift by 1/T: exact stabilizer)
//   S2_i = sum_{j!=i, lab_j==lab_i} cos_ij
//   cnt_i = 2*hist[lab_i] - 1
//
// Pipeline:
//   1) labels_kernel   : gather labels + histogram (1 block)
//   2) normalize_kernel: row-normalize features into g_norm
//   3) gram_kernel     : tiled 128x128x32 fp32 GEMM-like pass with fused
//                        exp/label-masked reduction epilogue; per-(split,row)
//                        partials written deterministically (no float atomics)
//   4) final_kernel    : combine partials -> scalar loss
// ---------------------------------------------------------------------------

#define NTPS   2
#define NPATCH 4096
#define MROWS  8192          // NTPS*NPATCH
#define CDIM   256
#define HSEG   128
#define NCE_T  0.07f
#define INV_T  (1.0f / NCE_T)

#define BM 128
#define BN 128
#define BK 32
#define NSPLIT 16            // col-splits; 64 row tiles x 16 = 1024 blocks
#define TILES_PER_SPLIT (64 / NSPLIT)   // col tiles per block = 4

__device__ float g_norm[MROWS * CDIM];       // normalized features (8 MB)
__device__ int   g_lab[NPATCH];
__device__ int   g_hist[8];
__device__ float g_S1p[NSPLIT][MROWS];       // per-split partials
__device__ float g_S2p[NSPLIT][MROWS];

// ---------------------------------------------------------------------------
// 1) labels + histogram (single block)
// ---------------------------------------------------------------------------
__global__ void labels_kernel(const int* __restrict__ seg,
                              const int* __restrict__ coords,
                              const int* __restrict__ crw,
                              const int* __restrict__ crh,
                              const int* __restrict__ crd) {
    __shared__ int sh_hist[8];
    int t = threadIdx.x;
    if (t < 8) sh_hist[t] = 0;
    __syncthreads();
    int cw = *crw, ch = *crh, cd = *crd;
    for (int p = t; p < NPATCH; p += blockDim.x) {
        int cx = coords[p * 3 + 0];
        int cy = coords[p * 3 + 1];
        int cz = coords[p * 3 + 2];
        int ix = (cx * HSEG) / cw;
        int iy = (cy * HSEG) / ch;
        int iz = (cz * HSEG) / cd;
        int l = seg[(ix * HSEG + iy) * HSEG + iz];
        g_lab[p] = l;
        atomicAdd(&sh_hist[l & 7], 1);
    }
    __syncthreads();
    if (t < 8) g_hist[t] = sh_hist[t];
}

// ---------------------------------------------------------------------------
// 2) row-normalize: one warp per row
// ---------------------------------------------------------------------------
__global__ void normalize_kernel(const float* __restrict__ f) {
    int warp = (blockIdx.x * blockDim.x + threadIdx.x) >> 5;
    int lane = threadIdx.x & 31;
    if (warp >= MROWS) return;
    const float4* src = (const float4*)(f + (size_t)warp * CDIM);
    float4 v0 = src[lane];
    float4 v1 = src[lane + 32];
    float ss = v0.x * v0.x + v0.y * v0.y + v0.z * v0.z + v0.w * v0.w
             + v1.x * v1.x + v1.y * v1.y + v1.z * v1.z + v1.w * v1.w;
    #pragma unroll
    for (int o = 16; o > 0; o >>= 1)
        ss += __shfl_xor_sync(0xffffffffu, ss, o);
    float inv = rsqrtf(fmaxf(ss, 1e-24f));
    v0.x *= inv; v0.y *= inv; v0.z *= inv; v0.w *= inv;
    v1.x *= inv; v1.y *= inv; v1.z *= inv; v1.w *= inv;
    float4* dst = (float4*)(g_norm + (size_t)warp * CDIM);
    dst[lane]      = v0;
    dst[lane + 32] = v1;
}

// ---------------------------------------------------------------------------
// 3) Gram + fused epilogue
//    grid = (64 row tiles, NSPLIT). 256 threads (16x16), 8x8 register tile.
// ---------------------------------------------------------------------------
__global__ __launch_bounds__(256, 2) void gram_kernel() {
    __shared__ float As[BK][BM + 4];   // transposed: As[k][row]
    __shared__ float Bs[BK][BN + 4];   // transposed: Bs[k][col]
    __shared__ int   labCol[BN];

    int tid = threadIdx.x;
    int tx = tid & 15;
    int ty = tid >> 4;
    int rowBase = blockIdx.x * BM;
    int split   = blockIdx.y;

    float s1[8], s2[8];
    int myLab[8];
    #pragma unroll
    for (int r = 0; r < 8; r++) {
        s1[r] = 0.0f;
        s2[r] = 0.0f;
        myLab[r] = g_lab[(rowBase + ty * 8 + r) & (NPATCH - 1)];
    }

    for (int t = 0; t < TILES_PER_SPLIT; t++) {
        int colBase = (split * TILES_PER_SPLIT + t) * BN;

        __syncthreads();   // previous tile's epilogue done before labCol reuse
        if (tid < BN)
            labCol[tid] = g_lab[(colBase + tid) & (NPATCH - 1)];

        float acc[8][8];
        #pragma unroll
        for (int r = 0; r < 8; r++)
            #pragma unroll
            for (int c = 0; c < 8; c++)
                acc[r][c] = 0.0f;

        for (int kb = 0; kb < CDIM; kb += BK) {
            __syncthreads();   // previous compute done before overwriting smem
            #pragma unroll
            for (int i = 0; i < 4; i++) {
                int idx = tid + i * 256;          // 0..1023
                int row = idx >> 3;               // 0..127
                int k4  = (idx & 7) * 4;          // 0,4,..,28
                float4 a = *(const float4*)(g_norm + (size_t)(rowBase + row) * CDIM + kb + k4);
                As[k4 + 0][row] = a.x;
                As[k4 + 1][row] = a.y;
                As[k4 + 2][row] = a.z;
                As[k4 + 3][row] = a.w;
                float4 b = *(const float4*)(g_norm + (size_t)(colBase + row) * CDIM + kb + k4);
                Bs[k4 + 0][row] = b.x;
                Bs[k4 + 1][row] = b.y;
                Bs[k4 + 2][row] = b.z;
                Bs[k4 + 3][row] = b.w;
            }
            __syncthreads();

            #pragma unroll 8
            for (int k = 0; k < BK; k++) {
                float a[8], b[8];
                *(float4*)(a)     = *(const float4*)&As[k][ty * 8];
                *(float4*)(a + 4) = *(const float4*)&As[k][ty * 8 + 4];
                *(float4*)(b)     = *(const float4*)&Bs[k][tx * 8];
                *(float4*)(b + 4) = *(const float4*)&Bs[k][tx * 8 + 4];
                #pragma unroll
                for (int r = 0; r < 8; r++)
                    #pragma unroll
                    for (int c = 0; c < 8; c++)
                        acc[r][c] = fmaf(a[r], b[c], acc[r][c]);
            }
        }

        // fused epilogue: exp-sum + label-masked cos-sum
        int lc[8];
        #pragma unroll
        for (int c = 0; c < 8; c++) lc[c] = labCol[tx * 8 + c];

        #pragma unroll
        for (int r = 0; r < 8; r++) {
            int gi = rowBase + ty * 8 + r;
            float a1 = 0.0f, a2 = 0.0f;
            #pragma unroll
            for (int c = 0; c < 8; c++) {
                int gj = colBase + tx * 8 + c;
                float cv = acc[r][c];
                if (gi != gj) {
                    a1 += __expf((cv - 1.0f) * INV_T);
                    if (lc[c] == myLab[r]) a2 += cv;
                }
            }
            s1[r] += a1;
            s2[r] += a2;
        }
    }

    // reduce across the 16 tx-lanes sharing each row (one half-warp per ty)
    int lane = tid & 31;
    #pragma unroll
    for (int r = 0; r < 8; r++) {
        float v1 = s1[r], v2 = s2[r];
        #pragma unroll
        for (int o = 8; o > 0; o >>= 1) {
            v1 += __shfl_xor_sync(0xffffffffu, v1, o);
            v2 += __shfl_xor_sync(0xffffffffu, v2, o);
        }
        if ((lane & 15) == 0) {
            int row = rowBase + ty * 8 + r;
            g_S1p[split][row] = v1;
            g_S2p[split][row] = v2;
        }
    }
}

// ---------------------------------------------------------------------------
// 4) final reduction -> scalar loss
// ---------------------------------------------------------------------------
__global__ void final_kernel(float* __restrict__ out) {
    __shared__ float sh[256];
    float local = 0.0f;
    for (int r = threadIdx.x; r < MROWS; r += 256) {
        float S1 = 0.0f, S2 = 0.0f;
        #pragma unroll
        for (int s = 0; s < NSPLIT; s++) {
            S1 += g_S1p[s][r];
            S2 += g_S2p[s][r];
        }
        int lb = g_lab[r & (NPATCH - 1)] & 7;
        float cnt = (float)(2 * g_hist[lb] - 1);
        // loss_i = log(S1) - (S2 - cnt) * (1/T) / cnt
        local += logf(S1) - (S2 - cnt) * (INV_T / cnt);
    }
    sh[threadIdx.x] = local;
    __syncthreads();
    for (int o = 128; o > 0; o >>= 1) {
        if (threadIdx.x < o) sh[threadIdx.x] += sh[threadIdx.x + o];
        __syncthreads();
    }
    if (threadIdx.x == 0)
        out[0] = sh[0] / (float)MROWS;
}

// ---------------------------------------------------------------------------
extern "C" void kernel_launch(void* const* d_in, const int* in_sizes, int n_in,
                              void* d_out, int out_size) {
    const float* features = (const float*)d_in[0];
    const int*   seg      = (const int*)d_in[1];
    const int*   coords   = (const int*)d_in[2];
    const int*   crw      = (const int*)d_in[3];
    const int*   crh      = (const int*)d_in[4];
    const int*   crd      = (const int*)d_in[5];
    float* out = (float*)d_out;

    labels_kernel<<<1, 256>>>(seg, coords, crw, crh, crd);
    normalize_kernel<<<MROWS / 8, 256>>>(features);   // 8 warps/block, 1 row/warp
    dim3 grid(MROWS / BM, NSPLIT);                    // (64, 16)
    gram_kernel<<<grid, 256>>>();
    final_kernel<<<1, 256>>>(out);
}

// round 6
// speedup vs baseline: 5.6312x; 5.6312x over previous
#include <cuda_runtime.h>
#include <cuda_bf16.h>
#include <math.h>
#include <stdint.h>

// ---------------------------------------------------------------------------
// SupPatchNCELoss — GB300 (sm_103a), round 5
//
// loss = mean_i [ log S1_i - (S2_i - cnt_i) * (1/T) / cnt_i ]
//   S1_i = sum_{j!=i} exp((cos_ij - 1)/T)
//   S2_i = sum_{j!=i, lab_j==lab_i} cos_ij
//   cnt_i = 2*hist[lab_i] - 1
//
// Gram matrix via legacy tensor cores (mma.sync m16n8k8 tf32), SYMMETRIC
// tiling: only tile pairs (I,J) with I<=J are computed; each off-diagonal
// tile contributes to row sums of tile I (row-side) and of tile J (col-side).
// Deterministic partials: slot = other tile index, each (slot,row) written
// exactly once. No float atomics anywhere.
// ---------------------------------------------------------------------------

#define NPATCH 4096
#define MROWS  8192
#define CDIM   256
#define HSEG   128
#define INV_T  (1.0f / 0.07f)

#define NT 64                 // 8192 / 128 tiles per dim
#define NPAIRS (NT * (NT + 1) / 2)   // 2080

__device__ float g_norm[MROWS * CDIM];       // tf32-rounded normalized features
__device__ int   g_lab[NPATCH];
__device__ int   g_hist[8];
__device__ float g_S1p[NT][MROWS];           // partials: [other-tile][row]
__device__ float g_S2p[NT][MROWS];
__device__ float g_part[64];

// ---------------------------------------------------------------------------
__device__ __forceinline__ float tf32r(float x) {
    float r;
    asm("cvt.rna.tf32.f32 %0, %1;" : "=f"(r) : "f"(x));
    return r;
}

__device__ __forceinline__ void mma_tf32(float c[4], const unsigned a[4],
                                         const unsigned b[2]) {
    asm volatile(
        "mma.sync.aligned.m16n8k8.row.col.f32.tf32.tf32.f32 "
        "{%0,%1,%2,%3}, {%4,%5,%6,%7}, {%8,%9}, {%0,%1,%2,%3};\n"
        : "+f"(c[0]), "+f"(c[1]), "+f"(c[2]), "+f"(c[3])
        : "r"(a[0]), "r"(a[1]), "r"(a[2]), "r"(a[3]), "r"(b[0]), "r"(b[1]));
}

// ---------------------------------------------------------------------------
// 1) labels + histogram (single block)
// ---------------------------------------------------------------------------
__global__ void labels_kernel(const int* __restrict__ seg,
                              const int* __restrict__ coords,
                              const int* __restrict__ crw,
                              const int* __restrict__ crh,
                              const int* __restrict__ crd) {
    __shared__ int sh_hist[8];
    int t = threadIdx.x;
    if (t < 8) sh_hist[t] = 0;
    __syncthreads();
    int cw = *crw, ch = *crh, cd = *crd;
    for (int p = t; p < NPATCH; p += blockDim.x) {
        int cx = coords[p * 3 + 0];
        int cy = coords[p * 3 + 1];
        int cz = coords[p * 3 + 2];
        int ix = (cx * HSEG) / cw;
        int iy = (cy * HSEG) / ch;
        int iz = (cz * HSEG) / cd;
        int l = seg[(ix * HSEG + iy) * HSEG + iz];
        g_lab[p] = l;
        atomicAdd(&sh_hist[l & 7], 1);
    }
    __syncthreads();
    if (t < 8) g_hist[t] = sh_hist[t];
}

// ---------------------------------------------------------------------------
// 2) row-normalize + round to tf32: one warp per row
// ---------------------------------------------------------------------------
__global__ void normalize_kernel(const float* __restrict__ f) {
    int warp = (blockIdx.x * blockDim.x + threadIdx.x) >> 5;
    int lane = threadIdx.x & 31;
    if (warp >= MROWS) return;
    const float4* src = (const float4*)(f + (size_t)warp * CDIM);
    float4 v0 = src[lane];
    float4 v1 = src[lane + 32];
    float ss = v0.x * v0.x + v0.y * v0.y + v0.z * v0.z + v0.w * v0.w
             + v1.x * v1.x + v1.y * v1.y + v1.z * v1.z + v1.w * v1.w;
    #pragma unroll
    for (int o = 16; o > 0; o >>= 1)
        ss += __shfl_xor_sync(0xffffffffu, ss, o);
    float inv = rsqrtf(fmaxf(ss, 1e-24f));
    v0.x = tf32r(v0.x * inv); v0.y = tf32r(v0.y * inv);
    v0.z = tf32r(v0.z * inv); v0.w = tf32r(v0.w * inv);
    v1.x = tf32r(v1.x * inv); v1.y = tf32r(v1.y * inv);
    v1.z = tf32r(v1.z * inv); v1.w = tf32r(v1.w * inv);
    float4* dst = (float4*)(g_norm + (size_t)warp * CDIM);
    dst[lane]      = v0;
    dst[lane + 32] = v1;
}

// ---------------------------------------------------------------------------
// 3) symmetric Gram + fused epilogue (tensor cores)
//    2080 blocks, 256 threads = 8 warps (wy in {0,1}, wx in {0..3}),
//    warp tile 64x32, block tile 128x128, K staged in chunks of 32.
// ---------------------------------------------------------------------------
__global__ __launch_bounds__(256, 2) void gram_kernel() {
    __shared__ float As[128][36];   // [m][k], stride 36 => conflict-free frags
    __shared__ float Bs[128][36];   // [n][k]
    __shared__ int   labR[128], labC[128];
    __shared__ float sR1[4][128], sR2[4][128];   // per-wx row partials
    __shared__ float sC1[2][128], sC2[2][128];   // per-wy col partials

    // linear block -> (I, J) with I <= J
    int b = blockIdx.x;
    int I = 0;
    while (b >= NT - I) { b -= NT - I; I++; }
    int J = I + b;
    int rowBase = I * 128, colBase = J * 128;

    int tid  = threadIdx.x;
    int lane = tid & 31, w = tid >> 5;
    int wy = w >> 2, wx = w & 3;
    int g = lane >> 2, t4 = lane & 3;

    if (tid < 128) labR[tid] = g_lab[(rowBase + tid) & (NPATCH - 1)];
    else           labC[tid - 128] = g_lab[(colBase + tid - 128) & (NPATCH - 1)];

    float acc[4][4][4];
    #pragma unroll
    for (int mi = 0; mi < 4; mi++)
        #pragma unroll
        for (int ni = 0; ni < 4; ni++)
            #pragma unroll
            for (int q = 0; q < 4; q++) acc[mi][ni][q] = 0.0f;

    for (int kb = 0; kb < CDIM; kb += 32) {
        __syncthreads();
        #pragma unroll
        for (int i = 0; i < 4; i++) {
            int lin = tid + i * 256;          // 0..1023
            int row = lin >> 3;               // 0..127
            int kq  = (lin & 7) * 4;          // 0,4,..,28
            float4 a = *(const float4*)(g_norm + (size_t)(rowBase + row) * CDIM + kb + kq);
            *(float4*)&As[row][kq] = a;
            float4 bb = *(const float4*)(g_norm + (size_t)(colBase + row) * CDIM + kb + kq);
            *(float4*)&Bs[row][kq] = bb;
        }
        __syncthreads();

        #pragma unroll
        for (int kk = 0; kk < 32; kk += 8) {
            unsigned af[4][4], bf[4][2];
            #pragma unroll
            for (int mi = 0; mi < 4; mi++) {
                int r = wy * 64 + mi * 16 + g;
                af[mi][0] = __float_as_uint(As[r][kk + t4]);
                af[mi][1] = __float_as_uint(As[r + 8][kk + t4]);
                af[mi][2] = __float_as_uint(As[r][kk + t4 + 4]);
                af[mi][3] = __float_as_uint(As[r + 8][kk + t4 + 4]);
            }
            #pragma unroll
            for (int ni = 0; ni < 4; ni++) {
                int c = wx * 32 + ni * 8 + g;
                bf[ni][0] = __float_as_uint(Bs[c][kk + t4]);
                bf[ni][1] = __float_as_uint(Bs[c][kk + t4 + 4]);
            }
            #pragma unroll
            for (int mi = 0; mi < 4; mi++)
                #pragma unroll
                for (int ni = 0; ni < 4; ni++)
                    mma_tf32(acc[mi][ni], af[mi], bf[ni]);
        }
    }

    // ---- fused epilogue: exp-sum + label-masked cos-sum, both sides ----
    float cs1[4][2], cs2[4][2];
    #pragma unroll
    for (int ni = 0; ni < 4; ni++) {
        cs1[ni][0] = 0.f; cs1[ni][1] = 0.f;
        cs2[ni][0] = 0.f; cs2[ni][1] = 0.f;
    }
    bool diag = (I == J);

    #pragma unroll
    for (int mi = 0; mi < 4; mi++) {
        float rs1[2] = {0.f, 0.f}, rs2[2] = {0.f, 0.f};
        int lr0 = wy * 64 + mi * 16 + g;      // local rows
        int lr1 = lr0 + 8;
        int labr0 = labR[lr0], labr1 = labR[lr1];
        #pragma unroll
        for (int ni = 0; ni < 4; ni++) {
            int lc0 = wx * 32 + ni * 8 + 2 * t4;
            int lc1 = lc0 + 1;
            int labc0 = labC[lc0], labc1 = labC[lc1];
            #pragma unroll
            for (int q = 0; q < 4; q++) {
                int lr = (q & 2) ? lr1 : lr0;
                int lc = (q & 1) ? lc1 : lc0;
                int lbr = (q & 2) ? labr1 : labr0;
                int lbc = (q & 1) ? labc1 : labc0;
                float v = acc[mi][ni][q];
                bool self = diag && (lr == lc);
                float e = __expf((v - 1.0f) * INV_T);
                if (!self) {
                    rs1[(q >> 1)] += e;
                    cs1[ni][(q & 1)] += e;
                    if (lbr == lbc) {
                        rs2[(q >> 1)] += v;
                        cs2[ni][(q & 1)] += v;
                    }
                }
            }
        }
        // row-side reduce over t4 (lanes sharing the same row)
        #pragma unroll
        for (int h = 0; h < 2; h++) {
            float v1 = rs1[h], v2 = rs2[h];
            v1 += __shfl_xor_sync(0xffffffffu, v1, 1);
            v1 += __shfl_xor_sync(0xffffffffu, v1, 2);
            v2 += __shfl_xor_sync(0xffffffffu, v2, 1);
            v2 += __shfl_xor_sync(0xffffffffu, v2, 2);
            if (t4 == 0) {
                int lr = wy * 64 + mi * 16 + h * 8 + g;
                sR1[wx][lr] = v1;
                sR2[wx][lr] = v2;
            }
        }
    }

    // col-side reduce over g (lanes sharing the same column)
    #pragma unroll
    for (int ni = 0; ni < 4; ni++) {
        #pragma unroll
        for (int h = 0; h < 2; h++) {
            float v1 = cs1[ni][h], v2 = cs2[ni][h];
            v1 += __shfl_xor_sync(0xffffffffu, v1, 4);
            v1 += __shfl_xor_sync(0xffffffffu, v1, 8);
            v1 += __shfl_xor_sync(0xffffffffu, v1, 16);
            v2 += __shfl_xor_sync(0xffffffffu, v2, 4);
            v2 += __shfl_xor_sync(0xffffffffu, v2, 8);
            v2 += __shfl_xor_sync(0xffffffffu, v2, 16);
            if (g == 0) {
                int lc = wx * 32 + ni * 8 + 2 * t4 + h;
                sC1[wy][lc] = v1;
                sC2[wy][lc] = v2;
            }
        }
    }
    __syncthreads();

    // deterministic partial writes: slot = other tile index
    if (tid < 128) {
        int r = tid;
        g_S1p[J][rowBase + r] = sR1[0][r] + sR1[1][r] + sR1[2][r] + sR1[3][r];
        g_S2p[J][rowBase + r] = sR2[0][r] + sR2[1][r] + sR2[2][r] + sR2[3][r];
    } else if (I < J) {
        int c = tid - 128;
        g_S1p[I][colBase + c] = sC1[0][c] + sC1[1][c];
        g_S2p[I][colBase + c] = sC2[0][c] + sC2[1][c];
    }
}

// ---------------------------------------------------------------------------
// 4) final reduction: 64 blocks x 128 threads, 1 row per thread
// ---------------------------------------------------------------------------
__global__ void final1_kernel() {
    __shared__ float sh[128];
    int row = blockIdx.x * 128 + threadIdx.x;
    float S1 = 0.0f, S2 = 0.0f;
    #pragma unroll
    for (int s = 0; s < NT; s++) {
        S1 += g_S1p[s][row];
        S2 += g_S2p[s][row];
    }
    int lb = g_lab[row & (NPATCH - 1)] & 7;
    float cnt = (float)(2 * g_hist[lb] - 1);
    sh[threadIdx.x] = logf(S1) - (S2 - cnt) * (INV_T / cnt);
    __syncthreads();
    for (int o = 64; o > 0; o >>= 1) {
        if (threadIdx.x < o) sh[threadIdx.x] += sh[threadIdx.x + o];
        __syncthreads();
    }
    if (threadIdx.x == 0) g_part[blockIdx.x] = sh[0];
}

__global__ void final2_kernel(float* __restrict__ out) {
    __shared__ float sh[64];
    sh[threadIdx.x] = g_part[threadIdx.x];
    __syncthreads();
    for (int o = 32; o > 0; o >>= 1) {
        if (threadIdx.x < o) sh[threadIdx.x] += sh[threadIdx.x + o];
        __syncthreads();
    }
    if (threadIdx.x == 0) out[0] = sh[0] / (float)MROWS;
}

// ---------------------------------------------------------------------------
extern "C" void kernel_launch(void* const* d_in, const int* in_sizes, int n_in,
                              void* d_out, int out_size) {
    const float* features = (const float*)d_in[0];
    const int*   seg      = (const int*)d_in[1];
    const int*   coords   = (const int*)d_in[2];
    const int*   crw      = (const int*)d_in[3];
    const int*   crh      = (const int*)d_in[4];
    const int*   crd      = (const int*)d_in[5];
    float* out = (float*)d_out;

    labels_kernel<<<1, 256>>>(seg, coords, crw, crh, crd);
    normalize_kernel<<<MROWS / 8, 256>>>(features);
    gram_kernel<<<NPAIRS, 256>>>();
    final1_kernel<<<64, 128>>>();
    final2_kernel<<<1, 64>>>(out);
}

// round 7
// speedup vs baseline: 5.8546x; 1.0397x over previous
#include <cuda_runtime.h>
#include <cuda_bf16.h>
#include <math.h>
#include <stdint.h>

// ---------------------------------------------------------------------------
// SupPatchNCELoss — GB300 (sm_103a), round 6
//
// loss = mean_i [ log S1_i - (S2_i - cnt_i) * (1/T) / cnt_i ]
//   S1_i = sum_{j!=i} exp((cos_ij - 1)/T)
//   S2_i = sum_{j!=i, lab_j==lab_i} cos_ij
//   cnt_i = 2*hist[lab_i] - 1
//
// R6 change vs R5: double-buffered cp.async (LDGSTS) pipeline in gram_kernel
// (removes the per-stage LDG latency exposure of the single-buffered loop),
// dynamic smem ring; final reduction widened to 128 blocks.
// ---------------------------------------------------------------------------

#define NPATCH 4096
#define MROWS  8192
#define CDIM   256
#define HSEG   128
#define INV_T  (1.0f / 0.07f)

#define NT 64                        // 8192/128 tiles per dim
#define NPAIRS (NT * (NT + 1) / 2)   // 2080

#define BK 32
#define SKD 36                       // smem k-stride (conflict-free)
#define STAGE_F (128 * SKD)          // floats per tile-buffer

__device__ float g_norm[MROWS * CDIM];
__device__ int   g_lab[NPATCH];
__device__ int   g_hist[8];
__device__ float g_S1p[NT][MROWS];
__device__ float g_S2p[NT][MROWS];
__device__ float g_part[128];

// ---------------------------------------------------------------------------
__device__ __forceinline__ float tf32r(float x) {
    float r;
    asm("cvt.rna.tf32.f32 %0, %1;" : "=f"(r) : "f"(x));
    return r;
}

__device__ __forceinline__ void mma_tf32(float c[4], const unsigned a[4],
                                         const unsigned b[2]) {
    asm volatile(
        "mma.sync.aligned.m16n8k8.row.col.f32.tf32.tf32.f32 "
        "{%0,%1,%2,%3}, {%4,%5,%6,%7}, {%8,%9}, {%0,%1,%2,%3};\n"
        : "+f"(c[0]), "+f"(c[1]), "+f"(c[2]), "+f"(c[3])
        : "r"(a[0]), "r"(a[1]), "r"(a[2]), "r"(a[3]), "r"(b[0]), "r"(b[1]));
}

__device__ __forceinline__ void cp16(float* dst_smem, const float* src) {
    unsigned d = (unsigned)__cvta_generic_to_shared(dst_smem);
    asm volatile("cp.async.cg.shared.global [%0], [%1], 16;\n"
                 :: "r"(d), "l"(src));
}
#define CP_COMMIT() asm volatile("cp.async.commit_group;\n" ::: "memory")
#define CP_WAIT(n)  asm volatile("cp.async.wait_group %0;\n" :: "n"(n) : "memory")

// ---------------------------------------------------------------------------
// 1) labels + histogram (single block)
// ---------------------------------------------------------------------------
__global__ void labels_kernel(const int* __restrict__ seg,
                              const int* __restrict__ coords,
                              const int* __restrict__ crw,
                              const int* __restrict__ crh,
                              const int* __restrict__ crd) {
    __shared__ int sh_hist[8];
    int t = threadIdx.x;
    if (t < 8) sh_hist[t] = 0;
    __syncthreads();
    int cw = *crw, ch = *crh, cd = *crd;
    for (int p = t; p < NPATCH; p += blockDim.x) {
        int cx = coords[p * 3 + 0];
        int cy = coords[p * 3 + 1];
        int cz = coords[p * 3 + 2];
        int ix = (cx * HSEG) / cw;
        int iy = (cy * HSEG) / ch;
        int iz = (cz * HSEG) / cd;
        int l = seg[(ix * HSEG + iy) * HSEG + iz];
        g_lab[p] = l;
        atomicAdd(&sh_hist[l & 7], 1);
    }
    __syncthreads();
    if (t < 8) g_hist[t] = sh_hist[t];
}

// ---------------------------------------------------------------------------
// 2) row-normalize + round to tf32: one warp per row
// ---------------------------------------------------------------------------
__global__ void normalize_kernel(const float* __restrict__ f) {
    int warp = (blockIdx.x * blockDim.x + threadIdx.x) >> 5;
    int lane = threadIdx.x & 31;
    if (warp >= MROWS) return;
    const float4* src = (const float4*)(f + (size_t)warp * CDIM);
    float4 v0 = src[lane];
    float4 v1 = src[lane + 32];
    float ss = v0.x * v0.x + v0.y * v0.y + v0.z * v0.z + v0.w * v0.w
             + v1.x * v1.x + v1.y * v1.y + v1.z * v1.z + v1.w * v1.w;
    #pragma unroll
    for (int o = 16; o > 0; o >>= 1)
        ss += __shfl_xor_sync(0xffffffffu, ss, o);
    float inv = rsqrtf(fmaxf(ss, 1e-24f));
    v0.x = tf32r(v0.x * inv); v0.y = tf32r(v0.y * inv);
    v0.z = tf32r(v0.z * inv); v0.w = tf32r(v0.w * inv);
    v1.x = tf32r(v1.x * inv); v1.y = tf32r(v1.y * inv);
    v1.z = tf32r(v1.z * inv); v1.w = tf32r(v1.w * inv);
    float4* dst = (float4*)(g_norm + (size_t)warp * CDIM);
    dst[lane]      = v0;
    dst[lane + 32] = v1;
}

// ---------------------------------------------------------------------------
// 3) symmetric Gram + fused epilogue, double-buffered cp.async pipeline
//    2080 blocks, 256 threads = 8 warps (wy in {0,1}, wx in {0..3}),
//    warp tile 64x32, block tile 128x128, K staged in chunks of 32.
// ---------------------------------------------------------------------------
__global__ __launch_bounds__(256, 2) void gram_kernel() {
    extern __shared__ float dyn[];
    // dyn layout: As[2][128][SKD] then Bs[2][128][SKD]
    float* Abuf = dyn;
    float* Bbuf = dyn + 2 * STAGE_F;
    #define AS(s, r, k) Abuf[(s) * STAGE_F + (r) * SKD + (k)]
    #define BS(s, r, k) Bbuf[(s) * STAGE_F + (r) * SKD + (k)]

    __shared__ int   labR[128], labC[128];
    __shared__ float sR1[4][128], sR2[4][128];
    __shared__ float sC1[2][128], sC2[2][128];

    // linear block -> (I, J) with I <= J
    int b = blockIdx.x;
    int I = 0;
    while (b >= NT - I) { b -= NT - I; I++; }
    int J = I + b;
    int rowBase = I * 128, colBase = J * 128;

    int tid  = threadIdx.x;
    int lane = tid & 31, w = tid >> 5;
    int wy = w >> 2, wx = w & 3;
    int g = lane >> 2, t4 = lane & 3;

    if (tid < 128) labR[tid] = g_lab[(rowBase + tid) & (NPATCH - 1)];
    else           labC[tid - 128] = g_lab[(colBase + tid - 128) & (NPATCH - 1)];

    // per-thread stage-load coordinates (4 x 16B per tile per stage)
    int srow[4], skq[4];
    #pragma unroll
    for (int i = 0; i < 4; i++) {
        int lin = tid + i * 256;
        srow[i] = lin >> 3;
        skq[i]  = (lin & 7) * 4;
    }

    // prefetch stage 0 (kb = 0)
    #pragma unroll
    for (int i = 0; i < 4; i++) {
        cp16(&AS(0, srow[i], skq[i]),
             g_norm + (size_t)(rowBase + srow[i]) * CDIM + skq[i]);
        cp16(&BS(0, srow[i], skq[i]),
             g_norm + (size_t)(colBase + srow[i]) * CDIM + skq[i]);
    }
    CP_COMMIT();

    float acc[4][4][4];
    #pragma unroll
    for (int mi = 0; mi < 4; mi++)
        #pragma unroll
        for (int ni = 0; ni < 4; ni++)
            #pragma unroll
            for (int q = 0; q < 4; q++) acc[mi][ni][q] = 0.0f;

    #pragma unroll 1
    for (int kbi = 0; kbi < CDIM / BK; kbi++) {
        int cur = kbi & 1;
        if (kbi < CDIM / BK - 1) {
            int kb = (kbi + 1) * BK;
            #pragma unroll
            for (int i = 0; i < 4; i++) {
                cp16(&AS(cur ^ 1, srow[i], skq[i]),
                     g_norm + (size_t)(rowBase + srow[i]) * CDIM + kb + skq[i]);
                cp16(&BS(cur ^ 1, srow[i], skq[i]),
                     g_norm + (size_t)(colBase + srow[i]) * CDIM + kb + skq[i]);
            }
            CP_COMMIT();
            CP_WAIT(1);     // stage `cur` complete; next stage may be in flight
        } else {
            CP_WAIT(0);
        }
        __syncthreads();

        #pragma unroll
        for (int kk = 0; kk < BK; kk += 8) {
            unsigned af[4][4], bf[4][2];
            #pragma unroll
            for (int mi = 0; mi < 4; mi++) {
                int r = wy * 64 + mi * 16 + g;
                af[mi][0] = __float_as_uint(AS(cur, r, kk + t4));
                af[mi][1] = __float_as_uint(AS(cur, r + 8, kk + t4));
                af[mi][2] = __float_as_uint(AS(cur, r, kk + t4 + 4));
                af[mi][3] = __float_as_uint(AS(cur, r + 8, kk + t4 + 4));
            }
            #pragma unroll
            for (int ni = 0; ni < 4; ni++) {
                int c = wx * 32 + ni * 8 + g;
                bf[ni][0] = __float_as_uint(BS(cur, c, kk + t4));
                bf[ni][1] = __float_as_uint(BS(cur, c, kk + t4 + 4));
            }
            #pragma unroll
            for (int mi = 0; mi < 4; mi++)
                #pragma unroll
                for (int ni = 0; ni < 4; ni++)
                    mma_tf32(acc[mi][ni], af[mi], bf[ni]);
        }
        __syncthreads();   // compute done before next iter overwrites `cur`
    }

    // ---- fused epilogue: exp-sum + label-masked cos-sum, both sides ----
    float cs1[4][2], cs2[4][2];
    #pragma unroll
    for (int ni = 0; ni < 4; ni++) {
        cs1[ni][0] = 0.f; cs1[ni][1] = 0.f;
        cs2[ni][0] = 0.f; cs2[ni][1] = 0.f;
    }
    bool diag = (I == J);

    #pragma unroll
    for (int mi = 0; mi < 4; mi++) {
        float rs1[2] = {0.f, 0.f}, rs2[2] = {0.f, 0.f};
        int lr0 = wy * 64 + mi * 16 + g;
        int lr1 = lr0 + 8;
        int labr0 = labR[lr0], labr1 = labR[lr1];
        #pragma unroll
        for (int ni = 0; ni < 4; ni++) {
            int lc0 = wx * 32 + ni * 8 + 2 * t4;
            int lc1 = lc0 + 1;
            int labc0 = labC[lc0], labc1 = labC[lc1];
            #pragma unroll
            for (int q = 0; q < 4; q++) {
                int lr = (q & 2) ? lr1 : lr0;
                int lc = (q & 1) ? lc1 : lc0;
                int lbr = (q & 2) ? labr1 : labr0;
                int lbc = (q & 1) ? labc1 : labc0;
                float v = acc[mi][ni][q];
                bool self = diag && (lr == lc);
                float e = __expf((v - 1.0f) * INV_T);
                if (!self) {
                    rs1[(q >> 1)] += e;
                    cs1[ni][(q & 1)] += e;
                    if (lbr == lbc) {
                        rs2[(q >> 1)] += v;
                        cs2[ni][(q & 1)] += v;
                    }
                }
            }
        }
        #pragma unroll
        for (int h = 0; h < 2; h++) {
            float v1 = rs1[h], v2 = rs2[h];
            v1 += __shfl_xor_sync(0xffffffffu, v1, 1);
            v1 += __shfl_xor_sync(0xffffffffu, v1, 2);
            v2 += __shfl_xor_sync(0xffffffffu, v2, 1);
            v2 += __shfl_xor_sync(0xffffffffu, v2, 2);
            if (t4 == 0) {
                int lr = wy * 64 + mi * 16 + h * 8 + g;
                sR1[wx][lr] = v1;
                sR2[wx][lr] = v2;
            }
        }
    }

    #pragma unroll
    for (int ni = 0; ni < 4; ni++) {
        #pragma unroll
        for (int h = 0; h < 2; h++) {
            float v1 = cs1[ni][h], v2 = cs2[ni][h];
            v1 += __shfl_xor_sync(0xffffffffu, v1, 4);
            v1 += __shfl_xor_sync(0xffffffffu, v1, 8);
            v1 += __shfl_xor_sync(0xffffffffu, v1, 16);
            v2 += __shfl_xor_sync(0xffffffffu, v2, 4);
            v2 += __shfl_xor_sync(0xffffffffu, v2, 8);
            v2 += __shfl_xor_sync(0xffffffffu, v2, 16);
            if (g == 0) {
                int lc = wx * 32 + ni * 8 + 2 * t4 + h;
                sC1[wy][lc] = v1;
                sC2[wy][lc] = v2;
            }
        }
    }
    __syncthreads();

    // deterministic partial writes: slot = other tile index
    if (tid < 128) {
        int r = tid;
        g_S1p[J][rowBase + r] = sR1[0][r] + sR1[1][r] + sR1[2][r] + sR1[3][r];
        g_S2p[J][rowBase + r] = sR2[0][r] + sR2[1][r] + sR2[2][r] + sR2[3][r];
    } else if (I < J) {
        int c = tid - 128;
        g_S1p[I][colBase + c] = sC1[0][c] + sC1[1][c];
        g_S2p[I][colBase + c] = sC2[0][c] + sC2[1][c];
    }
    #undef AS
    #undef BS
}

// ---------------------------------------------------------------------------
// 4) final reduction: 128 blocks x 64 threads, 1 row per thread
// ---------------------------------------------------------------------------
__global__ void final1_kernel() {
    __shared__ float sh[64];
    int row = blockIdx.x * 64 + threadIdx.x;
    float S1a = 0.0f, S2a = 0.0f, S1b = 0.0f, S2b = 0.0f;
    #pragma unroll
    for (int s = 0; s < NT; s += 2) {
        S1a += g_S1p[s][row];
        S2a += g_S2p[s][row];
        S1b += g_S1p[s + 1][row];
        S2b += g_S2p[s + 1][row];
    }
    float S1 = S1a + S1b, S2 = S2a + S2b;
    int lb = g_lab[row & (NPATCH - 1)] & 7;
    float cnt = (float)(2 * g_hist[lb] - 1);
    sh[threadIdx.x] = logf(S1) - (S2 - cnt) * (INV_T / cnt);
    __syncthreads();
    for (int o = 32; o > 0; o >>= 1) {
        if (threadIdx.x < o) sh[threadIdx.x] += sh[threadIdx.x + o];
        __syncthreads();
    }
    if (threadIdx.x == 0) g_part[blockIdx.x] = sh[0];
}

__global__ void final2_kernel(float* __restrict__ out) {
    __shared__ float sh[128];
    sh[threadIdx.x] = g_part[threadIdx.x];
    __syncthreads();
    for (int o = 64; o > 0; o >>= 1) {
        if (threadIdx.x < o) sh[threadIdx.x] += sh[threadIdx.x + o];
        __syncthreads();
    }
    if (threadIdx.x == 0) out[0] = sh[0] / (float)MROWS;
}

// ---------------------------------------------------------------------------
extern "C" void kernel_launch(void* const* d_in, const int* in_sizes, int n_in,
                              void* d_out, int out_size) {
    const float* features = (const float*)d_in[0];
    const int*   seg      = (const int*)d_in[1];
    const int*   coords   = (const int*)d_in[2];
    const int*   crw      = (const int*)d_in[3];
    const int*   crh      = (const int*)d_in[4];
    const int*   crd      = (const int*)d_in[5];
    float* out = (float*)d_out;

    const int dynBytes = 4 * STAGE_F * sizeof(float);   // 73728
    static bool attr_set = false;
    if (!attr_set) {
        cudaFuncSetAttribute(gram_kernel,
                             cudaFuncAttributeMaxDynamicSharedMemorySize,
                             dynBytes);
        attr_set = true;
    }

    labels_kernel<<<1, 256>>>(seg, coords, crw, crh, crd);
    normalize_kernel<<<MROWS / 8, 256>>>(features);
    gram_kernel<<<NPAIRS, 256, dynBytes>>>();
    final1_kernel<<<128, 64>>>();
    final2_kernel<<<1, 128>>>(out);
}

// round 8
// speedup vs baseline: 5.8668x; 1.0021x over previous
#include <cuda_runtime.h>
#include <cuda_bf16.h>
#include <math.h>
#include <stdint.h>

// ---------------------------------------------------------------------------
// SupPatchNCELoss — GB300 (sm_103a), round 6
//
// loss = mean_i [ log S1_i - (S2_i - cnt_i) * (1/T) / cnt_i ]
//   S1_i = sum_{j!=i} exp((cos_ij - 1)/T)
//   S2_i = sum_{j!=i, lab_j==lab_i} cos_ij
//   cnt_i = 2*hist[lab_i] - 1
//
// R6 change vs R5: double-buffered cp.async (LDGSTS) pipeline in gram_kernel
// (removes the per-stage LDG latency exposure of the single-buffered loop),
// dynamic smem ring; final reduction widened to 128 blocks.
// ---------------------------------------------------------------------------

#define NPATCH 4096
#define MROWS  8192
#define CDIM   256
#define HSEG   128
#define INV_T  (1.0f / 0.07f)

#define NT 64                        // 8192/128 tiles per dim
#define NPAIRS (NT * (NT + 1) / 2)   // 2080

#define BK 32
#define SKD 36                       // smem k-stride (conflict-free)
#define STAGE_F (128 * SKD)          // floats per tile-buffer

__device__ float g_norm[MROWS * CDIM];
__device__ int   g_lab[NPATCH];
__device__ int   g_hist[8];
__device__ float g_S1p[NT][MROWS];
__device__ float g_S2p[NT][MROWS];
__device__ float g_part[128];

// ---------------------------------------------------------------------------
__device__ __forceinline__ float tf32r(float x) {
    float r;
    asm("cvt.rna.tf32.f32 %0, %1;" : "=f"(r) : "f"(x));
    return r;
}

__device__ __forceinline__ void mma_tf32(float c[4], const unsigned a[4],
                                         const unsigned b[2]) {
    asm volatile(
        "mma.sync.aligned.m16n8k8.row.col.f32.tf32.tf32.f32 "
        "{%0,%1,%2,%3}, {%4,%5,%6,%7}, {%8,%9}, {%0,%1,%2,%3};\n"
        : "+f"(c[0]), "+f"(c[1]), "+f"(c[2]), "+f"(c[3])
        : "r"(a[0]), "r"(a[1]), "r"(a[2]), "r"(a[3]), "r"(b[0]), "r"(b[1]));
}

__device__ __forceinline__ void cp16(float* dst_smem, const float* src) {
    unsigned d = (unsigned)__cvta_generic_to_shared(dst_smem);
    asm volatile("cp.async.cg.shared.global [%0], [%1], 16;\n"
                 :: "r"(d), "l"(src));
}
#define CP_COMMIT() asm volatile("cp.async.commit_group;\n" ::: "memory")
#define CP_WAIT(n)  asm volatile("cp.async.wait_group %0;\n" :: "n"(n) : "memory")

// ---------------------------------------------------------------------------
// 1) labels + histogram (single block)
// ---------------------------------------------------------------------------
__global__ void labels_kernel(const int* __restrict__ seg,
                              const int* __restrict__ coords,
                              const int* __restrict__ crw,
                              const int* __restrict__ crh,
                              const int* __restrict__ crd) {
    __shared__ int sh_hist[8];
    int t = threadIdx.x;
    if (t < 8) sh_hist[t] = 0;
    __syncthreads();
    int cw = *crw, ch = *crh, cd = *crd;
    for (int p = t; p < NPATCH; p += blockDim.x) {
        int cx = coords[p * 3 + 0];
        int cy = coords[p * 3 + 1];
        int cz = coords[p * 3 + 2];
        int ix = (cx * HSEG) / cw;
        int iy = (cy * HSEG) / ch;
        int iz = (cz * HSEG) / cd;
        int l = seg[(ix * HSEG + iy) * HSEG + iz];
        g_lab[p] = l;
        atomicAdd(&sh_hist[l & 7], 1);
    }
    __syncthreads();
    if (t < 8) g_hist[t] = sh_hist[t];
}

// ---------------------------------------------------------------------------
// 2) row-normalize + round to tf32: one warp per row
// ---------------------------------------------------------------------------
__global__ void normalize_kernel(const float* __restrict__ f) {
    int warp = (blockIdx.x * blockDim.x + threadIdx.x) >> 5;
    int lane = threadIdx.x & 31;
    if (warp >= MROWS) return;
    const float4* src = (const float4*)(f + (size_t)warp * CDIM);
    float4 v0 = src[lane];
    float4 v1 = src[lane + 32];
    float ss = v0.x * v0.x + v0.y * v0.y + v0.z * v0.z + v0.w * v0.w
             + v1.x * v1.x + v1.y * v1.y + v1.z * v1.z + v1.w * v1.w;
    #pragma unroll
    for (int o = 16; o > 0; o >>= 1)
        ss += __shfl_xor_sync(0xffffffffu, ss, o);
    float inv = rsqrtf(fmaxf(ss, 1e-24f));
    v0.x = tf32r(v0.x * inv); v0.y = tf32r(v0.y * inv);
    v0.z = tf32r(v0.z * inv); v0.w = tf32r(v0.w * inv);
    v1.x = tf32r(v1.x * inv); v1.y = tf32r(v1.y * inv);
    v1.z = tf32r(v1.z * inv); v1.w = tf32r(v1.w * inv);
    float4* dst = (float4*)(g_norm + (size_t)warp * CDIM);
    dst[lane]      = v0;
    dst[lane + 32] = v1;
}

// ---------------------------------------------------------------------------
// 3) symmetric Gram + fused epilogue, double-buffered cp.async pipeline
//    2080 blocks, 256 threads = 8 warps (wy in {0,1}, wx in {0..3}),
//    warp tile 64x32, block tile 128x128, K staged in chunks of 32.
// ---------------------------------------------------------------------------
__global__ __launch_bounds__(256, 2) void gram_kernel() {
    extern __shared__ float dyn[];
    // dyn layout: As[2][128][SKD] then Bs[2][128][SKD]
    float* Abuf = dyn;
    float* Bbuf = dyn + 2 * STAGE_F;
    #define AS(s, r, k) Abuf[(s) * STAGE_F + (r) * SKD + (k)]
    #define BS(s, r, k) Bbuf[(s) * STAGE_F + (r) * SKD + (k)]

    __shared__ int   labR[128], labC[128];
    __shared__ float sR1[4][128], sR2[4][128];
    __shared__ float sC1[2][128], sC2[2][128];

    // linear block -> (I, J) with I <= J
    int b = blockIdx.x;
    int I = 0;
    while (b >= NT - I) { b -= NT - I; I++; }
    int J = I + b;
    int rowBase = I * 128, colBase = J * 128;

    int tid  = threadIdx.x;
    int lane = tid & 31, w = tid >> 5;
    int wy = w >> 2, wx = w & 3;
    int g = lane >> 2, t4 = lane & 3;

    if (tid < 128) labR[tid] = g_lab[(rowBase + tid) & (NPATCH - 1)];
    else           labC[tid - 128] = g_lab[(colBase + tid - 128) & (NPATCH - 1)];

    // per-thread stage-load coordinates (4 x 16B per tile per stage)
    int srow[4], skq[4];
    #pragma unroll
    for (int i = 0; i < 4; i++) {
        int lin = tid + i * 256;
        srow[i] = lin >> 3;
        skq[i]  = (lin & 7) * 4;
    }

    // prefetch stage 0 (kb = 0)
    #pragma unroll
    for (int i = 0; i < 4; i++) {
        cp16(&AS(0, srow[i], skq[i]),
             g_norm + (size_t)(rowBase + srow[i]) * CDIM + skq[i]);
        cp16(&BS(0, srow[i], skq[i]),
             g_norm + (size_t)(colBase + srow[i]) * CDIM + skq[i]);
    }
    CP_COMMIT();

    float acc[4][4][4];
    #pragma unroll
    for (int mi = 0; mi < 4; mi++)
        #pragma unroll
        for (int ni = 0; ni < 4; ni++)
            #pragma unroll
            for (int q = 0; q < 4; q++) acc[mi][ni][q] = 0.0f;

    #pragma unroll 1
    for (int kbi = 0; kbi < CDIM / BK; kbi++) {
        int cur = kbi & 1;
        if (kbi < CDIM / BK - 1) {
            int kb = (kbi + 1) * BK;
            #pragma unroll
            for (int i = 0; i < 4; i++) {
                cp16(&AS(cur ^ 1, srow[i], skq[i]),
                     g_norm + (size_t)(rowBase + srow[i]) * CDIM + kb + skq[i]);
                cp16(&BS(cur ^ 1, srow[i], skq[i]),
                     g_norm + (size_t)(colBase + srow[i]) * CDIM + kb + skq[i]);
            }
            CP_COMMIT();
            CP_WAIT(1);     // stage `cur` complete; next stage may be in flight
        } else {
            CP_WAIT(0);
        }
        __syncthreads();

        #pragma unroll
        for (int kk = 0; kk < BK; kk += 8) {
            unsigned af[4][4], bf[4][2];
            #pragma unroll
            for (int mi = 0; mi < 4; mi++) {
                int r = wy * 64 + mi * 16 + g;
                af[mi][0] = __float_as_uint(AS(cur, r, kk + t4));
                af[mi][1] = __float_as_uint(AS(cur, r + 8, kk + t4));
                af[mi][2] = __float_as_uint(AS(cur, r, kk + t4 + 4));
                af[mi][3] = __float_as_uint(AS(cur, r + 8, kk + t4 + 4));
            }
            #pragma unroll
            for (int ni = 0; ni < 4; ni++) {
                int c = wx * 32 + ni * 8 + g;
                bf[ni][0] = __float_as_uint(BS(cur, c, kk + t4));
                bf[ni][1] = __float_as_uint(BS(cur, c, kk + t4 + 4));
            }
            #pragma unroll
            for (int mi = 0; mi < 4; mi++)
                #pragma unroll
                for (int ni = 0; ni < 4; ni++)
                    mma_tf32(acc[mi][ni], af[mi], bf[ni]);
        }
        __syncthreads();   // compute done before next iter overwrites `cur`
    }

    // ---- fused epilogue: exp-sum + label-masked cos-sum, both sides ----
    float cs1[4][2], cs2[4][2];
    #pragma unroll
    for (int ni = 0; ni < 4; ni++) {
        cs1[ni][0] = 0.f; cs1[ni][1] = 0.f;
        cs2[ni][0] = 0.f; cs2[ni][1] = 0.f;
    }
    bool diag = (I == J);

    #pragma unroll
    for (int mi = 0; mi < 4; mi++) {
        float rs1[2] = {0.f, 0.f}, rs2[2] = {0.f, 0.f};
        int lr0 = wy * 64 + mi * 16 + g;
        int lr1 = lr0 + 8;
        int labr0 = labR[lr0], labr1 = labR[lr1];
        #pragma unroll
        for (int ni = 0; ni < 4; ni++) {
            int lc0 = wx * 32 + ni * 8 + 2 * t4;
            int lc1 = lc0 + 1;
            int labc0 = labC[lc0], labc1 = labC[lc1];
            #pragma unroll
            for (int q = 0; q < 4; q++) {
                int lr = (q & 2) ? lr1 : lr0;
                int lc = (q & 1) ? lc1 : lc0;
                int lbr = (q & 2) ? labr1 : labr0;
                int lbc = (q & 1) ? labc1 : labc0;
                float v = acc[mi][ni][q];
                bool self = diag && (lr == lc);
                float e = __expf((v - 1.0f) * INV_T);
                if (!self) {
                    rs1[(q >> 1)] += e;
                    cs1[ni][(q & 1)] += e;
                    if (lbr == lbc) {
                        rs2[(q >> 1)] += v;
                        cs2[ni][(q & 1)] += v;
                    }
                }
            }
        }
        #pragma unroll
        for (int h = 0; h < 2; h++) {
            float v1 = rs1[h], v2 = rs2[h];
            v1 += __shfl_xor_sync(0xffffffffu, v1, 1);
            v1 += __shfl_xor_sync(0xffffffffu, v1, 2);
            v2 += __shfl_xor_sync(0xffffffffu, v2, 1);
            v2 += __shfl_xor_sync(0xffffffffu, v2, 2);
            if (t4 == 0) {
                int lr = wy * 64 + mi * 16 + h * 8 + g;
                sR1[wx][lr] = v1;
                sR2[wx][lr] = v2;
            }
        }
    }

    #pragma unroll
    for (int ni = 0; ni < 4; ni++) {
        #pragma unroll
        for (int h = 0; h < 2; h++) {
            float v1 = cs1[ni][h], v2 = cs2[ni][h];
            v1 += __shfl_xor_sync(0xffffffffu, v1, 4);
            v1 += __shfl_xor_sync(0xffffffffu, v1, 8);
            v1 += __shfl_xor_sync(0xffffffffu, v1, 16);
            v2 += __shfl_xor_sync(0xffffffffu, v2, 4);
            v2 += __shfl_xor_sync(0xffffffffu, v2, 8);
            v2 += __shfl_xor_sync(0xffffffffu, v2, 16);
            if (g == 0) {
                int lc = wx * 32 + ni * 8 + 2 * t4 + h;
                sC1[wy][lc] = v1;
                sC2[wy][lc] = v2;
            }
        }
    }
    __syncthreads();

    // deterministic partial writes: slot = other tile index
    if (tid < 128) {
        int r = tid;
        g_S1p[J][rowBase + r] = sR1[0][r] + sR1[1][r] + sR1[2][r] + sR1[3][r];
        g_S2p[J][rowBase + r] = sR2[0][r] + sR2[1][r] + sR2[2][r] + sR2[3][r];
    } else if (I < J) {
        int c = tid - 128;
        g_S1p[I][colBase + c] = sC1[0][c] + sC1[1][c];
        g_S2p[I][colBase + c] = sC2[0][c] + sC2[1][c];
    }
    #undef AS
    #undef BS
}

// ---------------------------------------------------------------------------
// 4) final reduction: 128 blocks x 64 threads, 1 row per thread
// ---------------------------------------------------------------------------
__global__ void final1_kernel() {
    __shared__ float sh[64];
    int row = blockIdx.x * 64 + threadIdx.x;
    float S1a = 0.0f, S2a = 0.0f, S1b = 0.0f, S2b = 0.0f;
    #pragma unroll
    for (int s = 0; s < NT; s += 2) {
        S1a += g_S1p[s][row];
        S2a += g_S2p[s][row];
        S1b += g_S1p[s + 1][row];
        S2b += g_S2p[s + 1][row];
    }
    float S1 = S1a + S1b, S2 = S2a + S2b;
    int lb = g_lab[row & (NPATCH - 1)] & 7;
    float cnt = (float)(2 * g_hist[lb] - 1);
    sh[threadIdx.x] = logf(S1) - (S2 - cnt) * (INV_T / cnt);
    __syncthreads();
    for (int o = 32; o > 0; o >>= 1) {
        if (threadIdx.x < o) sh[threadIdx.x] += sh[threadIdx.x + o];
        __syncthreads();
    }
    if (threadIdx.x == 0) g_part[blockIdx.x] = sh[0];
}

__global__ void final2_kernel(float* __restrict__ out) {
    __shared__ float sh[128];
    sh[threadIdx.x] = g_part[threadIdx.x];
    __syncthreads();
    for (int o = 64; o > 0; o >>= 1) {
        if (threadIdx.x < o) sh[threadIdx.x] += sh[threadIdx.x + o];
        __syncthreads();
    }
    if (threadIdx.x == 0) out[0] = sh[0] / (float)MROWS;
}

// ---------------------------------------------------------------------------
extern "C" void kernel_launch(void* const* d_in, const int* in_sizes, int n_in,
                              void* d_out, int out_size) {
    const float* features = (const float*)d_in[0];
    const int*   seg      = (const int*)d_in[1];
    const int*   coords   = (const int*)d_in[2];
    const int*   crw      = (const int*)d_in[3];
    const int*   crh      = (const int*)d_in[4];
    const int*   crd      = (const int*)d_in[5];
    float* out = (float*)d_out;

    const int dynBytes = 4 * STAGE_F * sizeof(float);   // 73728
    static bool attr_set = false;
    if (!attr_set) {
        cudaFuncSetAttribute(gram_kernel,
                             cudaFuncAttributeMaxDynamicSharedMemorySize,
                             dynBytes);
        attr_set = true;
    }

    labels_kernel<<<1, 256>>>(seg, coords, crw, crh, crd);
    normalize_kernel<<<MROWS / 8, 256>>>(features);
    gram_kernel<<<NPAIRS, 256, dynBytes>>>();
    final1_kernel<<<128, 64>>>();
    final2_kernel<<<1, 128>>>(out);
}